// round 7
// baseline (speedup 1.0000x reference)
#include <cuda_runtime.h>
#include <math.h>

typedef unsigned long long ull;

// Shapes
#define NROWS 4096
#define XLD   1184   // padded 1182 -> 1184 (news[1024] | price[158] | 2 zeros)
#define NPAIR 37     // 74 16-k tiles = 37 pairs of 32 k
#define WBLK  592    // (1184*128)/256 W-remap blocks (run first, hidden)
#define OFF_PRED 0
#define OFF_RW1  (NROWS)
#define OFF_HID  (NROWS + NROWS*64)
#define OFF_TK   (NROWS + 2*NROWS*64)
#define OFF_RW2  (NROWS + 2*NROWS*64 + NROWS*2)

// Scratch
__device__ float g_X[(size_t)NROWS * XLD];
__device__ float g_W2[(size_t)XLD * 128];   // remapped+padded router_W

// ---------------------------------------------------------------------------
// f32x2 helpers
// ---------------------------------------------------------------------------
__device__ __forceinline__ ull pk2(float v) {
    ull r; asm("mov.b64 %0, {%1,%1};" : "=l"(r) : "f"(v)); return r;
}
__device__ __forceinline__ void fma2(ull& d, ull a, ull b) {
    asm("fma.rn.f32x2 %0, %1, %2, %0;" : "+l"(d) : "l"(a), "l"(b));
}
__device__ __forceinline__ void unpk2(ull v, float& lo, float& hi) {
    asm("mov.b64 {%0,%1}, %2;" : "=f"(lo), "=f"(hi) : "l"(v));
}
union F4U { float4 f; ull u[2]; };

// ---------------------------------------------------------------------------
// Kernel 1: W-remap blocks FIRST (hide in memory wave), then news/price agg.
// ---------------------------------------------------------------------------
__global__ __launch_bounds__(256) void k_agg(const float* __restrict__ price,
                                             const float* __restrict__ news,
                                             const float* __restrict__ mask,
                                             const float* __restrict__ rW)
{
    int tid = threadIdx.x;
    if (blockIdx.x < WBLK) {                 // W remap
        int idx = blockIdx.x * 256 + tid;    // over 1184*128
        int k = idx >> 7, c = idx & 127;
        float v = 0.f;
        if (k < 1182) {
            int wr = (k < 1024) ? (k + 158) : (k - 1024);
            v = __ldg(rW + (size_t)wr * 128 + c);
        }
        g_W2[idx] = v;
        return;
    }
    int n = blockIdx.x - WBLK;

    const float* nf   = news  + (size_t)n * 32 * 1024 + tid * 4;
    const float* pf   = price + (size_t)n * 32 * 158;
    const float* mrow = mask  + n * 32;

    float4 acc = make_float4(0.f, 0.f, 0.f, 0.f);
    float msum = 0.f, pacc = 0.f;

#pragma unroll 8
    for (int t = 0; t < 32; ++t) {
        float m = __ldg(mrow + t);
        msum += m;
        float4 v = *(const float4*)(nf + t * 1024);
        acc.x = fmaf(m, v.x, acc.x);
        acc.y = fmaf(m, v.y, acc.y);
        acc.z = fmaf(m, v.z, acc.z);
        acc.w = fmaf(m, v.w, acc.w);
        if (tid < 158) pacc += __ldg(pf + t * 158 + tid);
    }

    float inv = 1.f / fmaxf(msum, 1e-6f);
    float* xr = g_X + (size_t)n * XLD;
    *(float4*)(xr + tid * 4) =
        make_float4(acc.x * inv, acc.y * inv, acc.z * inv, acc.w * inv);
    if (tid < 158)       xr[1024 + tid] = pacc * (1.f / 32.f);
    else if (tid < 160)  xr[1024 + tid] = 0.f;
}

// ---------------------------------------------------------------------------
// Kernel 2: router GEMM with in-block K-split-2 + FFMA2 4x8 thread tiles,
// double-buffered 32-k stages, then gate GEMM + top2 + sparse expert path.
// 128 blocks x 256 threads, 32 rows/block.
// Smem is phase-aliased: [Ws|Xs] during GEMM1  ->  [h|hid|part] after.
// ---------------------------------------------------------------------------
__global__ __launch_bounds__(256) void k_main(
    const float* __restrict__ rb,
    const float* __restrict__ gW,  const float* __restrict__ gb,
    const float* __restrict__ eW,  const float* __restrict__ eb,
    const float* __restrict__ wq,  const float* __restrict__ wqb,
    const float* __restrict__ wk,  const float* __restrict__ wkb,
    const float* __restrict__ wv,  const float* __restrict__ wvb,
    const float* __restrict__ wo,  const float* __restrict__ wob,
    float* __restrict__ out)
{
    __shared__ __align__(16) char smraw[41984];
    float* WsP  = (float*)smraw;                 // [2][32][128]  (GEMM1)
    float* XsP  = (float*)(smraw + 32768);       // [2][32][36]   (GEMM1)
    float* hP   = (float*)smraw;                 // [32][132]     (post)
    float* hidP = (float*)(smraw + 16896);       // [32][68]      (post)
    float* ptP  = (float*)(smraw + 25600);       // [32][128]     (post)

#define WS(s,k,c) WsP[((((s) << 5) + (k)) << 7) + (c)]
#define XS(s,k,r) XsP[(((s) << 5) + (k)) * 36 + (r)]
#define HS(r,c)   hP[(r) * 132 + (c)]
#define HID(r,c)  hidP[(r) * 68 + (c)]
#define PT(r,c)   ptP[((r) << 7) + (c)]

    const int tid  = threadIdx.x;
    const int lane = tid & 31;
    const int wid  = tid >> 5;
    const int row0 = blockIdx.x * 32;

    // compute mapping: half h covers full 32x128, k-range koff..koff+15
    const int half = wid >> 2;                       // 0 or 1
    const int hw   = wid & 3;                        // warp within half
    const int xrow = (((hw & 1) << 2) + (lane >> 3)) << 2;  // 0,4,..,28
    const int wcol = (((hw >> 1) << 3) + (lane & 7)) << 3;  // 0,8,..,120
    const int koff = half << 4;

    // loader mapping (all 256 threads load the 32-k stage pair)
    const int lxr = tid >> 3;          // X row 0..31
    const int lxk = (tid & 7) * 4;     // X k̂ base 0,4,..,28
    const int lwk = tid >> 3;          // W k̂ 0..31
    const int lwc = (tid & 7) * 16;    // W col 0,16,..,112
    const float* xsrc = g_X + (size_t)(row0 + lxr) * XLD + lxk;
    const float* wsrc = g_W2 + (size_t)lwk * 128 + lwc;

    ull acc[4][4];
#pragma unroll
    for (int r = 0; r < 4; ++r)
#pragma unroll
        for (int c = 0; c < 4; ++c) acc[r][c] = 0ull;

    float4 xpre, wpre0, wpre1, wpre2, wpre3;

    // ---- prologue: pair 0 load+store, pair 1 load --------------------------
    xpre  = *(const float4*)xsrc;
    wpre0 = *(const float4*)(wsrc);
    wpre1 = *(const float4*)(wsrc + 4);
    wpre2 = *(const float4*)(wsrc + 8);
    wpre3 = *(const float4*)(wsrc + 12);
    XS(0, lxk, lxr) = xpre.x;  XS(0, lxk + 1, lxr) = xpre.y;
    XS(0, lxk + 2, lxr) = xpre.z;  XS(0, lxk + 3, lxr) = xpre.w;
    *(float4*)&WS(0, lwk, lwc)      = wpre0;
    *(float4*)&WS(0, lwk, lwc + 4)  = wpre1;
    *(float4*)&WS(0, lwk, lwc + 8)  = wpre2;
    *(float4*)&WS(0, lwk, lwc + 12) = wpre3;
    xpre  = *(const float4*)(xsrc + 32);
    wpre0 = *(const float4*)(wsrc + 32 * 128);
    wpre1 = *(const float4*)(wsrc + 32 * 128 + 4);
    wpre2 = *(const float4*)(wsrc + 32 * 128 + 8);
    wpre3 = *(const float4*)(wsrc + 32 * 128 + 12);
    __syncthreads();

    // ---- main pipeline: 1 barrier / 32-k pair ------------------------------
#pragma unroll 1
    for (int p = 0; p < NPAIR; ++p) {
        const int s = p & 1;
        if (p + 1 < NPAIR) {
            XS(1 - s, lxk, lxr) = xpre.x;  XS(1 - s, lxk + 1, lxr) = xpre.y;
            XS(1 - s, lxk + 2, lxr) = xpre.z;  XS(1 - s, lxk + 3, lxr) = xpre.w;
            *(float4*)&WS(1 - s, lwk, lwc)      = wpre0;
            *(float4*)&WS(1 - s, lwk, lwc + 4)  = wpre1;
            *(float4*)&WS(1 - s, lwk, lwc + 8)  = wpre2;
            *(float4*)&WS(1 - s, lwk, lwc + 12) = wpre3;
        }
        if (p + 2 < NPAIR) {
            const size_t xo = (size_t)(p + 2) * 32;
            const size_t wo2 = xo * 128;
            xpre  = *(const float4*)(xsrc + xo);
            wpre0 = *(const float4*)(wsrc + wo2);
            wpre1 = *(const float4*)(wsrc + wo2 + 4);
            wpre2 = *(const float4*)(wsrc + wo2 + 8);
            wpre3 = *(const float4*)(wsrc + wo2 + 12);
        }
#pragma unroll
        for (int k = 0; k < 16; ++k) {
            F4U wu0, wu1;
            float4 xv = *(const float4*)&XS(s, koff + k, xrow);
            wu0.f = *(const float4*)&WS(s, koff + k, wcol);
            wu1.f = *(const float4*)&WS(s, koff + k, wcol + 4);
            ull xb0 = pk2(xv.x), xb1 = pk2(xv.y);
            ull xb2 = pk2(xv.z), xb3 = pk2(xv.w);
            fma2(acc[0][0], wu0.u[0], xb0);
            fma2(acc[0][1], wu0.u[1], xb0);
            fma2(acc[0][2], wu1.u[0], xb0);
            fma2(acc[0][3], wu1.u[1], xb0);
            fma2(acc[1][0], wu0.u[0], xb1);
            fma2(acc[1][1], wu0.u[1], xb1);
            fma2(acc[1][2], wu1.u[0], xb1);
            fma2(acc[1][3], wu1.u[1], xb1);
            fma2(acc[2][0], wu0.u[0], xb2);
            fma2(acc[2][1], wu0.u[1], xb2);
            fma2(acc[2][2], wu1.u[0], xb2);
            fma2(acc[2][3], wu1.u[1], xb2);
            fma2(acc[3][0], wu0.u[0], xb3);
            fma2(acc[3][1], wu0.u[1], xb3);
            fma2(acc[3][2], wu1.u[0], xb3);
            fma2(acc[3][3], wu1.u[1], xb3);
        }
        __syncthreads();
    }

    // ---- combine K-split halves, bias + tanh -> HS --------------------------
    if (half == 1) {
#pragma unroll
        for (int r = 0; r < 4; ++r)
#pragma unroll
            for (int cp = 0; cp < 4; ++cp) {
                float lo, hi;
                unpk2(acc[r][cp], lo, hi);
                PT(xrow + r, wcol + 2 * cp)     = lo;
                PT(xrow + r, wcol + 2 * cp + 1) = hi;
            }
    }
    __syncthreads();
    if (half == 0) {
#pragma unroll
        for (int r = 0; r < 4; ++r)
#pragma unroll
            for (int cp = 0; cp < 4; ++cp) {
                float lo, hi;
                unpk2(acc[r][cp], lo, hi);
                int c = wcol + 2 * cp;
                HS(xrow + r, c)     = tanhf(lo + PT(xrow + r, c)     + __ldg(rb + c));
                HS(xrow + r, c + 1) = tanhf(hi + PT(xrow + r, c + 1) + __ldg(rb + c + 1));
            }
    }
    __syncthreads();

    // ---------------- GEMM2: hidden = h @ gate_W (32x64) --------------------
    {
        const int rp = tid >> 4;            // rows 2rp, 2rp+1
        const int c0 = (tid & 15) * 4;
        float a0[4], a1[4];
#pragma unroll
        for (int j = 0; j < 4; ++j) { a0[j] = __ldg(gb + c0 + j); a1[j] = a0[j]; }
#pragma unroll 4
        for (int k = 0; k < 128; ++k) {
            float4 g = *(const float4*)(gW + (size_t)k * 64 + c0);
            float h0 = HS(2 * rp, k), h1 = HS(2 * rp + 1, k);
            a0[0] = fmaf(h0, g.x, a0[0]);  a1[0] = fmaf(h1, g.x, a1[0]);
            a0[1] = fmaf(h0, g.y, a0[1]);  a1[1] = fmaf(h1, g.y, a1[1]);
            a0[2] = fmaf(h0, g.z, a0[2]);  a1[2] = fmaf(h1, g.z, a1[2]);
            a0[3] = fmaf(h0, g.w, a0[3]);  a1[3] = fmaf(h1, g.w, a1[3]);
        }
        int n0 = row0 + 2 * rp;
        *(float4*)&HID(2 * rp, c0)     = make_float4(a0[0], a0[1], a0[2], a0[3]);
        *(float4*)&HID(2 * rp + 1, c0) = make_float4(a1[0], a1[1], a1[2], a1[3]);
        *(float4*)(out + OFF_HID + (size_t)n0 * 64 + c0) =
            make_float4(a0[0], a0[1], a0[2], a0[3]);
        *(float4*)(out + OFF_HID + (size_t)(n0 + 1) * 64 + c0) =
            make_float4(a1[0], a1[1], a1[2], a1[3]);
    }
    __syncthreads();

    // ---------------- Epilogue: top2 + routing + sparse expert path ---------
    const int L = lane & 7;
    const int r = wid * 4 + (lane >> 3);
    const int n = row0 + r;

    float v1 = -INFINITY, v2 = -INFINITY;
    int   i1 = 0, i2 = 0;
#pragma unroll
    for (int j = 0; j < 8; ++j) {
        int idx = L * 8 + j;
        float v = HID(r, idx);
        if (v > v1) { v2 = v1; i2 = i1; v1 = v; i1 = idx; }
        else if (v > v2) { v2 = v; i2 = idx; }
    }
#pragma unroll
    for (int d = 1; d <= 4; d <<= 1) {
        float b1 = __shfl_down_sync(0xffffffffu, v1, d, 8);
        int  bi1 = __shfl_down_sync(0xffffffffu, i1, d, 8);
        float b2 = __shfl_down_sync(0xffffffffu, v2, d, 8);
        int  bi2 = __shfl_down_sync(0xffffffffu, i2, d, 8);
        if (b1 > v1) {
            if (v1 >= b2) { v2 = v1; i2 = i1; }
            else          { v2 = b2; i2 = bi2; }
            v1 = b1; i1 = bi1;
        } else if (b1 > v2) {
            v2 = b1; i2 = bi1;
        }
    }
    float rw1 = 0.f, rw2 = 0.f;
    if (L == 0) {
        float e2 = expf(v2 - v1);
        float inv = 1.f / (1.f + e2);
        rw1 = inv;
        rw2 = e2 * inv;
    }
    i1  = __shfl_sync(0xffffffffu, i1, 0, 8);
    i2  = __shfl_sync(0xffffffffu, i2, 0, 8);
    rw1 = __shfl_sync(0xffffffffu, rw1, 0, 8);
    rw2 = __shfl_sync(0xffffffffu, rw2, 0, 8);

#pragma unroll
    for (int j = 0; j < 8; ++j) {
        int idx = L * 8 + j;
        float val = (idx == i1) ? rw1 : ((idx == i2) ? rw2 : 0.f);
        out[OFF_RW1 + (size_t)n * 64 + idx] = val;
        out[OFF_RW2 + (size_t)n * 64 + idx] = val;
    }
    if (L == 0) {
        out[OFF_TK + (size_t)n * 2 + 0] = (float)i1;
        out[OFF_TK + (size_t)n * 2 + 1] = (float)i2;
    }

    float pred = 0.f;
#pragma unroll
    for (int s = 0; s < 2; ++s) {
        int sel  = s ? i2 : i1;
        float rw = s ? rw2 : rw1;
        int g = sel >> 3, f = sel & 7;

        float eo = __ldg(eb + g * 8 + L);
        const float* ew = eW + (size_t)(g * 8 + L) * 64;
#pragma unroll 16
        for (int h = 0; h < 64; ++h)
            eo = fmaf(HID(r, h), __ldg(ew + h), eo);

        float qf = __ldg(wqb + g * 8 + L);
        float kf = __ldg(wkb + g * 8 + L);
        float vf = __ldg(wvb + g * 8 + L);
        const float* wqr = wq + (size_t)(g * 8 + L) * 8;
        const float* wkr = wk + (size_t)(g * 8 + L) * 8;
        const float* wvr = wv + (size_t)(g * 8 + L) * 8;
#pragma unroll
        for (int e = 0; e < 8; ++e) {
            float eoe = __shfl_sync(0xffffffffu, eo, e, 8);
            qf = fmaf(eoe, __ldg(wqr + e), qf);
            kf = fmaf(eoe, __ldg(wkr + e), kf);
            vf = fmaf(eoe, __ldg(wvr + e), vf);
        }
        float q8[8], k8[8], v8[8];
#pragma unroll
        for (int e = 0; e < 8; ++e) {
            q8[e] = __shfl_sync(0xffffffffu, qf, e, 8);
            k8[e] = __shfl_sync(0xffffffffu, kf, e, 8);
            v8[e] = __shfl_sync(0xffffffffu, vf, e, 8);
        }
        float s00 = 0.f, s01 = 0.f, s10 = 0.f, s11 = 0.f;
#pragma unroll
        for (int h = 0; h < 4; ++h) {
            float q0 = q8[2 * h], q1 = q8[2 * h + 1];
            float k0 = k8[2 * h], k1 = k8[2 * h + 1];
            s00 = fmaf(q0, k0, s00); s01 = fmaf(q0, k1, s01);
            s10 = fmaf(q1, k0, s10); s11 = fmaf(q1, k1, s11);
        }
        const float is2 = 0.70710678118654752440f;
        s00 *= is2; s01 *= is2; s10 *= is2; s11 *= is2;
        float m0 = fmaxf(s00, s01);
        float e00 = expf(s00 - m0), e01 = expf(s01 - m0);
        float n0 = 1.f / (e00 + e01);
        float a00 = e00 * n0, a01 = e01 * n0;
        float m1 = fmaxf(s10, s11);
        float e10 = expf(s10 - m1), e11 = expf(s11 - m1);
        float n1 = 1.f / (e10 + e11);
        float a10 = e10 * n1, a11 = e11 * n1;

        float att[8];
#pragma unroll
        for (int h = 0; h < 4; ++h) {
            att[2 * h]     = fmaf(a00, v8[2 * h], a01 * v8[2 * h + 1]);
            att[2 * h + 1] = fmaf(a10, v8[2 * h], a11 * v8[2 * h + 1]);
        }
        float aggf = __ldg(wob + g * 8 + f);
        const float* wor = wo + (size_t)(g * 8 + f) * 8;
#pragma unroll
        for (int e = 0; e < 8; ++e)
            aggf = fmaf(att[e], __ldg(wor + e), aggf);

        pred = fmaf(rw, aggf, pred);
    }
    if (L == 0) out[OFF_PRED + n] = pred;
}

// ---------------------------------------------------------------------------
extern "C" void kernel_launch(void* const* d_in, const int* in_sizes, int n_in,
                              void* d_out, int out_size)
{
    const float* price = (const float*)d_in[0];
    const float* news  = (const float*)d_in[1];
    const float* mask  = (const float*)d_in[2];
    const float* rW    = (const float*)d_in[3];
    const float* rb    = (const float*)d_in[4];
    const float* gW    = (const float*)d_in[5];
    const float* gb    = (const float*)d_in[6];
    const float* eW    = (const float*)d_in[7];
    const float* eb    = (const float*)d_in[8];
    const float* wq    = (const float*)d_in[9];
    const float* wqb   = (const float*)d_in[10];
    const float* wk    = (const float*)d_in[11];
    const float* wkb   = (const float*)d_in[12];
    const float* wv    = (const float*)d_in[13];
    const float* wvb   = (const float*)d_in[14];
    const float* wo    = (const float*)d_in[15];
    const float* wob   = (const float*)d_in[16];
    float* out = (float*)d_out;

    k_agg<<<WBLK + NROWS, 256>>>(price, news, mask, rW);
    k_main<<<NROWS / 32, 256>>>(rb, gW, gb, eW, eb,
                                wq, wqb, wk, wkb, wv, wvb, wo, wob, out);
}

// round 8
// speedup vs baseline: 1.0387x; 1.0387x over previous
#include <cuda_runtime.h>
#include <math.h>

typedef unsigned long long ull;

// Shapes
#define NROWS 4096
#define XLD   1184   // padded 1182 -> 1184 (news[1024] | price[158] | 2 zeros)
#define KSPL  4
#define KCH   296    // k per split  (4*296 = 1184)
#define KT    8      // k per smem tile
#define NTIL  37     // 296/8
#define WBLK  592    // (1184*128)/256 W-remap blocks (run first, hidden)
#define OFF_PRED 0
#define OFF_RW1  (NROWS)
#define OFF_HID  (NROWS + NROWS*64)
#define OFF_TK   (NROWS + 2*NROWS*64)
#define OFF_RW2  (NROWS + 2*NROWS*64 + NROWS*2)

// Scratch
__device__ float g_X[(size_t)NROWS * XLD];
__device__ float g_W2[(size_t)XLD * 128];             // remapped router_W
__device__ float g_part[(size_t)KSPL * NROWS * 128];  // split-K partials

// ---------------------------------------------------------------------------
// f32x2 helpers
// ---------------------------------------------------------------------------
__device__ __forceinline__ ull pk2(float v) {
    ull r; asm("mov.b64 %0, {%1,%1};" : "=l"(r) : "f"(v)); return r;
}
__device__ __forceinline__ void fma2(ull& d, ull a, ull b) {
    asm("fma.rn.f32x2 %0, %1, %2, %0;" : "+l"(d) : "l"(a), "l"(b));
}
__device__ __forceinline__ void unpk2(ull v, float& lo, float& hi) {
    asm("mov.b64 {%0,%1}, %2;" : "=f"(lo), "=f"(hi) : "l"(v));
}
union F4U { float4 f; ull u[2]; };

// ---------------------------------------------------------------------------
// Kernel 1: W-remap blocks FIRST (hidden in memory wave), then news/price agg.
// ---------------------------------------------------------------------------
__global__ __launch_bounds__(256) void k_agg(const float* __restrict__ price,
                                             const float* __restrict__ news,
                                             const float* __restrict__ mask,
                                             const float* __restrict__ rW)
{
    int tid = threadIdx.x;
    if (blockIdx.x < WBLK) {                 // W remap
        int idx = blockIdx.x * 256 + tid;
        int k = idx >> 7, c = idx & 127;
        float v = 0.f;
        if (k < 1182) {
            int wr = (k < 1024) ? (k + 158) : (k - 1024);
            v = __ldg(rW + (size_t)wr * 128 + c);
        }
        g_W2[idx] = v;
        return;
    }
    int n = blockIdx.x - WBLK;

    const float* nf   = news  + (size_t)n * 32 * 1024 + tid * 4;
    const float* pf   = price + (size_t)n * 32 * 158;
    const float* mrow = mask  + n * 32;

    float4 acc = make_float4(0.f, 0.f, 0.f, 0.f);
    float msum = 0.f, pacc = 0.f;

#pragma unroll 8
    for (int t = 0; t < 32; ++t) {
        float m = __ldg(mrow + t);
        msum += m;
        float4 v = *(const float4*)(nf + t * 1024);
        acc.x = fmaf(m, v.x, acc.x);
        acc.y = fmaf(m, v.y, acc.y);
        acc.z = fmaf(m, v.z, acc.z);
        acc.w = fmaf(m, v.w, acc.w);
        if (tid < 158) pacc += __ldg(pf + t * 158 + tid);
    }

    float inv = 1.f / fmaxf(msum, 1e-6f);
    float* xr = g_X + (size_t)n * XLD;
    *(float4*)(xr + tid * 4) =
        make_float4(acc.x * inv, acc.y * inv, acc.z * inv, acc.w * inv);
    if (tid < 158)       xr[1024 + tid] = pacc * (1.f / 32.f);
    else if (tid < 160)  xr[1024 + tid] = 0.f;
}

// ---------------------------------------------------------------------------
// Kernel 2: GEMM1 split-K. 512 blocks x 64 threads.
// block (rg, ks): rows rg*32..+31, k in [ks*296, ks*296+296) -> g_part[ks].
// Thread tile 8x8: per k 4 LDS.128 vs 32 FFMA2 (FMA-dominated).
// ---------------------------------------------------------------------------
__global__ __launch_bounds__(64) void k_gemm1()
{
    __shared__ __align__(16) float Xs[2][KT][36];    // [buf][k][row]
    __shared__ __align__(16) float Ws[2][KT][128];   // [buf][k][col]

    const int tid  = threadIdx.x;
    const int rg   = blockIdx.x >> 2;
    const int ks   = blockIdx.x & 3;
    const int row0 = rg * 32;
    const int k0   = ks * KCH;

    // loader mapping
    const int lxr = tid >> 1;            // X row 0..31
    const int lxq = (tid & 1) * 4;       // X k quad 0 or 4
    const int lwk = tid >> 3;            // W k 0..7
    const int lwc = (tid & 7) * 16;      // W col 0,16,..,112
    const float* xsrc = g_X + (size_t)(row0 + lxr) * XLD + k0 + lxq;
    const float* wsrc = g_W2 + (size_t)(k0 + lwk) * 128 + lwc;

    // compute mapping: 8 rows x 8 cols per thread
    const int r0 = ((tid >> 4) & 3) * 8;
    const int c0 = (tid & 15) * 8;

    ull acc[8][4];
#pragma unroll
    for (int r = 0; r < 8; ++r)
#pragma unroll
        for (int c = 0; c < 4; ++c) acc[r][c] = 0ull;

    float4 xpre, wpre0, wpre1, wpre2, wpre3;

    // prologue: tile 0 load+store, tile 1 load
    xpre  = *(const float4*)xsrc;
    wpre0 = *(const float4*)(wsrc);
    wpre1 = *(const float4*)(wsrc + 4);
    wpre2 = *(const float4*)(wsrc + 8);
    wpre3 = *(const float4*)(wsrc + 12);
    Xs[0][lxq][lxr] = xpre.x;  Xs[0][lxq + 1][lxr] = xpre.y;
    Xs[0][lxq + 2][lxr] = xpre.z;  Xs[0][lxq + 3][lxr] = xpre.w;
    *(float4*)&Ws[0][lwk][lwc]      = wpre0;
    *(float4*)&Ws[0][lwk][lwc + 4]  = wpre1;
    *(float4*)&Ws[0][lwk][lwc + 8]  = wpre2;
    *(float4*)&Ws[0][lwk][lwc + 12] = wpre3;
    xpre  = *(const float4*)(xsrc + KT);
    wpre0 = *(const float4*)(wsrc + KT * 128);
    wpre1 = *(const float4*)(wsrc + KT * 128 + 4);
    wpre2 = *(const float4*)(wsrc + KT * 128 + 8);
    wpre3 = *(const float4*)(wsrc + KT * 128 + 12);
    __syncthreads();

#pragma unroll 1
    for (int p = 0; p < NTIL; ++p) {
        const int s = p & 1;
        if (p + 1 < NTIL) {
            Xs[1 - s][lxq][lxr] = xpre.x;  Xs[1 - s][lxq + 1][lxr] = xpre.y;
            Xs[1 - s][lxq + 2][lxr] = xpre.z;  Xs[1 - s][lxq + 3][lxr] = xpre.w;
            *(float4*)&Ws[1 - s][lwk][lwc]      = wpre0;
            *(float4*)&Ws[1 - s][lwk][lwc + 4]  = wpre1;
            *(float4*)&Ws[1 - s][lwk][lwc + 8]  = wpre2;
            *(float4*)&Ws[1 - s][lwk][lwc + 12] = wpre3;
        }
        if (p + 2 < NTIL) {
            const int kb = (p + 2) * KT;
            xpre  = *(const float4*)(xsrc + kb);
            wpre0 = *(const float4*)(wsrc + (size_t)kb * 128);
            wpre1 = *(const float4*)(wsrc + (size_t)kb * 128 + 4);
            wpre2 = *(const float4*)(wsrc + (size_t)kb * 128 + 8);
            wpre3 = *(const float4*)(wsrc + (size_t)kb * 128 + 12);
        }
#pragma unroll
        for (int k = 0; k < KT; ++k) {
            F4U wa, wb;
            float4 xa = *(const float4*)&Xs[s][k][r0];
            float4 xb = *(const float4*)&Xs[s][k][r0 + 4];
            wa.f = *(const float4*)&Ws[s][k][c0];
            wb.f = *(const float4*)&Ws[s][k][c0 + 4];
            float xr[8] = {xa.x, xa.y, xa.z, xa.w, xb.x, xb.y, xb.z, xb.w};
#pragma unroll
            for (int r = 0; r < 8; ++r) {
                ull xp = pk2(xr[r]);
                fma2(acc[r][0], wa.u[0], xp);
                fma2(acc[r][1], wa.u[1], xp);
                fma2(acc[r][2], wb.u[0], xp);
                fma2(acc[r][3], wb.u[1], xp);
            }
        }
        __syncthreads();
    }

    // write partials
    float* dst = g_part + ((size_t)ks * NROWS + row0 + r0) * 128 + c0;
#pragma unroll
    for (int r = 0; r < 8; ++r) {
        float a, b, c, d, e, f, g, h;
        unpk2(acc[r][0], a, b);  unpk2(acc[r][1], c, d);
        unpk2(acc[r][2], e, f);  unpk2(acc[r][3], g, h);
        *(float4*)(dst + (size_t)r * 128)     = make_float4(a, b, c, d);
        *(float4*)(dst + (size_t)r * 128 + 4) = make_float4(e, f, g, h);
    }
}

// ---------------------------------------------------------------------------
// Kernel 3: combine partials + bias + tanh, GEMM2, top2 routing, expert path.
// 128 blocks x 256 threads, 32 rows/block.
// ---------------------------------------------------------------------------
__global__ __launch_bounds__(256) void k_rest(
    const float* __restrict__ rb,
    const float* __restrict__ gW,  const float* __restrict__ gb,
    const float* __restrict__ eW,  const float* __restrict__ eb,
    const float* __restrict__ wq,  const float* __restrict__ wqb,
    const float* __restrict__ wk,  const float* __restrict__ wkb,
    const float* __restrict__ wv,  const float* __restrict__ wvb,
    const float* __restrict__ wo,  const float* __restrict__ wob,
    float* __restrict__ out)
{
    __shared__ __align__(16) float h_s[32][132];   // tanh(router) outputs
    __shared__ __align__(16) float hid_s[32][68];  // gate outputs (hidden)

    const int tid  = threadIdx.x;
    const int lane = tid & 31;
    const int warp = tid >> 5;
    const int row0 = blockIdx.x * 32;

    // ---- combine 4 partials + bias + tanh -> h_s ----------------------------
    {
        const int r  = tid >> 3;           // 0..31
        const int c0 = (tid & 7) * 16;     // 16 cols per thread
        const float* p0 = g_part + ((size_t)0 * NROWS + row0 + r) * 128 + c0;
        float v[16];
#pragma unroll
        for (int q = 0; q < 4; ++q) {
            float4 a = *(const float4*)(p0 + q * 4);
            v[4 * q] = a.x; v[4 * q + 1] = a.y; v[4 * q + 2] = a.z; v[4 * q + 3] = a.w;
        }
#pragma unroll
        for (int s = 1; s < KSPL; ++s) {
            const float* ps = g_part + ((size_t)s * NROWS + row0 + r) * 128 + c0;
#pragma unroll
            for (int q = 0; q < 4; ++q) {
                float4 a = *(const float4*)(ps + q * 4);
                v[4 * q] += a.x; v[4 * q + 1] += a.y;
                v[4 * q + 2] += a.z; v[4 * q + 3] += a.w;
            }
        }
#pragma unroll
        for (int j = 0; j < 16; ++j)
            h_s[r][c0 + j] = tanhf(v[j] + __ldg(rb + c0 + j));
    }
    __syncthreads();

    // ---------------- GEMM2: hidden = h @ gate_W (32x64) --------------------
    {
        int r2 = tid >> 3;           // 0..31
        int j0 = (tid & 7) * 8;      // 0,8,..,56
        float ha[8];
#pragma unroll
        for (int j = 0; j < 8; ++j) ha[j] = __ldg(gb + j0 + j);
#pragma unroll 8
        for (int k = 0; k < 128; ++k) {
            float hv = h_s[r2][k];
            float4 g0 = *(const float4*)(gW + (size_t)k * 64 + j0);
            float4 g1 = *(const float4*)(gW + (size_t)k * 64 + j0 + 4);
            ha[0] = fmaf(hv, g0.x, ha[0]);
            ha[1] = fmaf(hv, g0.y, ha[1]);
            ha[2] = fmaf(hv, g0.z, ha[2]);
            ha[3] = fmaf(hv, g0.w, ha[3]);
            ha[4] = fmaf(hv, g1.x, ha[4]);
            ha[5] = fmaf(hv, g1.y, ha[5]);
            ha[6] = fmaf(hv, g1.z, ha[6]);
            ha[7] = fmaf(hv, g1.w, ha[7]);
        }
        int n = row0 + r2;
        float* ho = out + OFF_HID + (size_t)n * 64 + j0;
#pragma unroll
        for (int j = 0; j < 8; ++j) {
            hid_s[r2][j0 + j] = ha[j];
            ho[j] = ha[j];
        }
    }
    __syncthreads();

    // ---------------- Epilogue: top2 + routing + sparse expert path ---------
    const int L = lane & 7;
    const int r = warp * 4 + (lane >> 3);
    const int n = row0 + r;

    float v1 = -INFINITY, v2 = -INFINITY;
    int   i1 = 0, i2 = 0;
#pragma unroll
    for (int j = 0; j < 8; ++j) {
        int idx = L * 8 + j;
        float v = hid_s[r][idx];
        if (v > v1) { v2 = v1; i2 = i1; v1 = v; i1 = idx; }
        else if (v > v2) { v2 = v; i2 = idx; }
    }
#pragma unroll
    for (int d = 1; d <= 4; d <<= 1) {
        float b1 = __shfl_down_sync(0xffffffffu, v1, d, 8);
        int  bi1 = __shfl_down_sync(0xffffffffu, i1, d, 8);
        float b2 = __shfl_down_sync(0xffffffffu, v2, d, 8);
        int  bi2 = __shfl_down_sync(0xffffffffu, i2, d, 8);
        if (b1 > v1) {
            if (v1 >= b2) { v2 = v1; i2 = i1; }
            else          { v2 = b2; i2 = bi2; }
            v1 = b1; i1 = bi1;
        } else if (b1 > v2) {
            v2 = b1; i2 = bi1;
        }
    }
    float rw1 = 0.f, rw2 = 0.f;
    if (L == 0) {
        float e2 = expf(v2 - v1);
        float inv = 1.f / (1.f + e2);
        rw1 = inv;
        rw2 = e2 * inv;
    }
    i1  = __shfl_sync(0xffffffffu, i1, 0, 8);
    i2  = __shfl_sync(0xffffffffu, i2, 0, 8);
    rw1 = __shfl_sync(0xffffffffu, rw1, 0, 8);
    rw2 = __shfl_sync(0xffffffffu, rw2, 0, 8);

#pragma unroll
    for (int j = 0; j < 8; ++j) {
        int idx = L * 8 + j;
        float val = (idx == i1) ? rw1 : ((idx == i2) ? rw2 : 0.f);
        out[OFF_RW1 + (size_t)n * 64 + idx] = val;
        out[OFF_RW2 + (size_t)n * 64 + idx] = val;
    }
    if (L == 0) {
        out[OFF_TK + (size_t)n * 2 + 0] = (float)i1;
        out[OFF_TK + (size_t)n * 2 + 1] = (float)i2;
    }

    float pred = 0.f;
#pragma unroll
    for (int s = 0; s < 2; ++s) {
        int sel  = s ? i2 : i1;
        float rw = s ? rw2 : rw1;
        int g = sel >> 3, f = sel & 7;

        float eo = __ldg(eb + g * 8 + L);
        const float* ew = eW + (size_t)(g * 8 + L) * 64;
#pragma unroll 16
        for (int h = 0; h < 64; ++h)
            eo = fmaf(hid_s[r][h], __ldg(ew + h), eo);

        float qf = __ldg(wqb + g * 8 + L);
        float kf = __ldg(wkb + g * 8 + L);
        float vf = __ldg(wvb + g * 8 + L);
        const float* wqr = wq + (size_t)(g * 8 + L) * 8;
        const float* wkr = wk + (size_t)(g * 8 + L) * 8;
        const float* wvr = wv + (size_t)(g * 8 + L) * 8;
#pragma unroll
        for (int e = 0; e < 8; ++e) {
            float eoe = __shfl_sync(0xffffffffu, eo, e, 8);
            qf = fmaf(eoe, __ldg(wqr + e), qf);
            kf = fmaf(eoe, __ldg(wkr + e), kf);
            vf = fmaf(eoe, __ldg(wvr + e), vf);
        }
        float q8[8], k8[8], v8[8];
#pragma unroll
        for (int e = 0; e < 8; ++e) {
            q8[e] = __shfl_sync(0xffffffffu, qf, e, 8);
            k8[e] = __shfl_sync(0xffffffffu, kf, e, 8);
            v8[e] = __shfl_sync(0xffffffffu, vf, e, 8);
        }
        float s00 = 0.f, s01 = 0.f, s10 = 0.f, s11 = 0.f;
#pragma unroll
        for (int h = 0; h < 4; ++h) {
            float q0 = q8[2 * h], q1 = q8[2 * h + 1];
            float k0 = k8[2 * h], k1 = k8[2 * h + 1];
            s00 = fmaf(q0, k0, s00); s01 = fmaf(q0, k1, s01);
            s10 = fmaf(q1, k0, s10); s11 = fmaf(q1, k1, s11);
        }
        const float is2 = 0.70710678118654752440f;
        s00 *= is2; s01 *= is2; s10 *= is2; s11 *= is2;
        float m0 = fmaxf(s00, s01);
        float e00 = expf(s00 - m0), e01 = expf(s01 - m0);
        float n0 = 1.f / (e00 + e01);
        float a00 = e00 * n0, a01 = e01 * n0;
        float m1 = fmaxf(s10, s11);
        float e10 = expf(s10 - m1), e11 = expf(s11 - m1);
        float n1 = 1.f / (e10 + e11);
        float a10 = e10 * n1, a11 = e11 * n1;

        float att[8];
#pragma unroll
        for (int h = 0; h < 4; ++h) {
            att[2 * h]     = fmaf(a00, v8[2 * h], a01 * v8[2 * h + 1]);
            att[2 * h + 1] = fmaf(a10, v8[2 * h], a11 * v8[2 * h + 1]);
        }
        float aggf = __ldg(wob + g * 8 + f);
        const float* wor = wo + (size_t)(g * 8 + f) * 8;
#pragma unroll
        for (int e = 0; e < 8; ++e)
            aggf = fmaf(att[e], __ldg(wor + e), aggf);

        pred = fmaf(rw, aggf, pred);
    }
    if (L == 0) out[OFF_PRED + n] = pred;
}

// ---------------------------------------------------------------------------
extern "C" void kernel_launch(void* const* d_in, const int* in_sizes, int n_in,
                              void* d_out, int out_size)
{
    const float* price = (const float*)d_in[0];
    const float* news  = (const float*)d_in[1];
    const float* mask  = (const float*)d_in[2];
    const float* rW    = (const float*)d_in[3];
    const float* rb    = (const float*)d_in[4];
    const float* gW    = (const float*)d_in[5];
    const float* gb    = (const float*)d_in[6];
    const float* eW    = (const float*)d_in[7];
    const float* eb    = (const float*)d_in[8];
    const float* wq    = (const float*)d_in[9];
    const float* wqb   = (const float*)d_in[10];
    const float* wk    = (const float*)d_in[11];
    const float* wkb   = (const float*)d_in[12];
    const float* wv    = (const float*)d_in[13];
    const float* wvb   = (const float*)d_in[14];
    const float* wo    = (const float*)d_in[15];
    const float* wob   = (const float*)d_in[16];
    float* out = (float*)d_out;

    k_agg<<<WBLK + NROWS, 256>>>(price, news, mask, rW);
    k_gemm1<<<NROWS / 32 * KSPL, 64>>>();
    k_rest<<<NROWS / 32, 256>>>(rb, gW, gb, eW, eb,
                                wq, wqb, wk, wkb, wv, wvb, wo, wob, out);
}

// round 9
// speedup vs baseline: 1.1412x; 1.0987x over previous
#include <cuda_runtime.h>
#include <math.h>

typedef unsigned long long ull;

// Shapes
#define NROWS 4096
#define CHUNKS 37          // 37 x 32 = 1184 k (1024 news | 158 price | 2 pad)
#define OFF_PRED 0
#define OFF_RW1  (NROWS)
#define OFF_HID  (NROWS + NROWS*64)
#define OFF_TK   (NROWS + 2*NROWS*64)
#define OFF_RW2  (NROWS + 2*NROWS*64 + NROWS*2)

// ---------------------------------------------------------------------------
// f32x2 helpers
// ---------------------------------------------------------------------------
__device__ __forceinline__ ull pk2(float v) {
    ull r; asm("mov.b64 %0, {%1,%1};" : "=l"(r) : "f"(v)); return r;
}
__device__ __forceinline__ void fma2(ull& d, ull a, ull b) {
    asm("fma.rn.f32x2 %0, %1, %2, %0;" : "+l"(d) : "l"(a), "l"(b));
}
__device__ __forceinline__ void unpk2(ull v, float& lo, float& hi) {
    asm("mov.b64 {%0,%1}, %2;" : "=f"(lo), "=f"(hi) : "l"(v));
}
union F4U { float4 f; ull u[2]; };

// ---------------------------------------------------------------------------
// Fully fused kernel: streaming aggregation + router GEMM overlap, then
// gate GEMM + top2 routing + sparse expert path.
// 128 blocks x 256 threads, block owns 32 n-rows.
// ---------------------------------------------------------------------------
__global__ __launch_bounds__(256) void k_fused(
    const float* __restrict__ price, const float* __restrict__ news,
    const float* __restrict__ mask,  const float* __restrict__ rW,
    const float* __restrict__ rb,
    const float* __restrict__ gW,  const float* __restrict__ gb,
    const float* __restrict__ eW,  const float* __restrict__ eb,
    const float* __restrict__ wq,  const float* __restrict__ wqb,
    const float* __restrict__ wk,  const float* __restrict__ wkb,
    const float* __restrict__ wv,  const float* __restrict__ wvb,
    const float* __restrict__ wo,  const float* __restrict__ wob,
    float* __restrict__ out)
{
    __shared__ __align__(16) char smraw[46208];
    float* WsP  = (float*)smraw;                 // [2][32][128]  GEMM phase
    float* XsP  = (float*)(smraw + 32768);       // [2][32][36]   GEMM phase
    float* mwP  = (float*)(smraw + 41984);       // [32][33] mask weights
    float* hP   = (float*)smraw;                 // [32][132]     post phase
    float* hidP = (float*)(smraw + 16896);       // [32][68]      post phase

#define WSM(s,k,c) WsP[((((s) << 5) + (k)) << 7) + (c)]
#define XSM(s,k,r) XsP[(((s) << 5) + (k)) * 36 + (r)]
#define MW(r,t)    mwP[(r) * 33 + (t)]
#define HS(r,c)    hP[(r) * 132 + (c)]
#define HID(r,c)   hidP[(r) * 68 + (c)]

    const int tid  = threadIdx.x;
    const int lane = tid & 31;
    const int wid  = tid >> 5;
    const int row0 = blockIdx.x * 32;

    // ---- mask weights: w[r][t] = m[t] / clip(sum m) -------------------------
    if (tid < 32) {
        const float* mr = mask + (size_t)(row0 + tid) * 32;
        float s = 0.f;
#pragma unroll
        for (int t = 0; t < 32; ++t) s += __ldg(mr + t);
        float inv = 1.f / fmaxf(s, 1e-6f);
#pragma unroll
        for (int t = 0; t < 32; ++t) MW(tid, t) = __ldg(mr + t) * inv;
    }

    // aggregation mapping: thread (ar, aj) -> row ar, chunk-cols aj*4..+3
    const int ar = tid >> 3, aj = tid & 7;
    const float* nbase = news  + ((size_t)(row0 + ar) * 32) * 1024 + aj * 4;
    const float* pbase = price + ((size_t)(row0 + ar) * 32) * 158;
    // W loader mapping: thread loads k=wkk, cols wcc..wcc+15 of the chunk
    const int wkk = tid >> 3;
    const int wcc = (tid & 7) * 16;
    // GEMM mapping: thread -> rows wid*4..+3, cols lane*4..+3
    const int gr = wid << 2;
    const int gc = lane << 2;

    ull acc[4][2];
#pragma unroll
    for (int r = 0; r < 4; ++r) { acc[r][0] = 0ull; acc[r][1] = 0ull; }

    __syncthreads();   // mask weights visible

    // ---- prologue: aggregate + store chunk 0 (all news), load W chunk 0 ----
    {
        float4 wpre[4];
        const float* wp = rW + (size_t)(wkk + 158) * 128 + wcc;   // chunk0 news
#pragma unroll
        for (int q = 0; q < 4; ++q) wpre[q] = *(const float4*)(wp + 4 * q);

        float a0 = 0.f, a1 = 0.f, a2 = 0.f, a3 = 0.f;
#pragma unroll
        for (int t = 0; t < 32; ++t) {
            float4 nv = *(const float4*)(nbase + (size_t)t * 1024);
            float w = MW(ar, t);
            a0 = fmaf(w, nv.x, a0); a1 = fmaf(w, nv.y, a1);
            a2 = fmaf(w, nv.z, a2); a3 = fmaf(w, nv.w, a3);
        }
        XSM(0, aj * 4 + 0, ar) = a0;  XSM(0, aj * 4 + 1, ar) = a1;
        XSM(0, aj * 4 + 2, ar) = a2;  XSM(0, aj * 4 + 3, ar) = a3;
#pragma unroll
        for (int q = 0; q < 4; ++q)
            *(float4*)&WSM(0, wkk, wcc + 4 * q) = wpre[q];
    }
    __syncthreads();

    // ---- main loop: GEMM chunk c overlapped with aggregation of chunk c+1 --
#pragma unroll 1
    for (int c = 0; c < CHUNKS; ++c) {
        const int  s      = c & 1;
        const bool more   = (c + 1 < CHUNKS);
        const bool isNews = (c + 1 < 32);
        const int  kb     = (c + 1) * 32;

        float4 wpre[4];
        if (more) {
            int k = kb + wkk;
            int wr = (k < 1024) ? (k + 158) : (k - 1024);
            bool ok = (k < 1182);
            const float* wp = rW + (size_t)wr * 128 + wcc;
#pragma unroll
            for (int q = 0; q < 4; ++q)
                wpre[q] = ok ? *(const float4*)(wp + 4 * q)
                             : make_float4(0.f, 0.f, 0.f, 0.f);
        }

        float a0 = 0.f, a1 = 0.f, a2 = 0.f, a3 = 0.f;

#pragma unroll
        for (int b = 0; b < 4; ++b) {
            // issue next-chunk loads for this t-batch first (long latency)
            float4 nv[8];
            if (more) {
                if (isNews) {
#pragma unroll
                    for (int t8 = 0; t8 < 8; ++t8)
                        nv[t8] = *(const float4*)(nbase +
                                 (size_t)(b * 8 + t8) * 1024 + kb);
                } else {
                    const int d0 = kb - 1024 + aj * 4;
#pragma unroll
                    for (int t8 = 0; t8 < 8; ++t8) {
                        const float* pr = pbase + (size_t)(b * 8 + t8) * 158;
                        nv[t8].x = (d0 + 0 < 158) ? __ldg(pr + d0 + 0) : 0.f;
                        nv[t8].y = (d0 + 1 < 158) ? __ldg(pr + d0 + 1) : 0.f;
                        nv[t8].z = (d0 + 2 < 158) ? __ldg(pr + d0 + 2) : 0.f;
                        nv[t8].w = (d0 + 3 < 158) ? __ldg(pr + d0 + 3) : 0.f;
                    }
                }
            }
            // GEMM for k = b*8 .. b*8+7 on buffer s
#pragma unroll
            for (int k = b * 8; k < b * 8 + 8; ++k) {
                float4 xv = *(const float4*)&XSM(s, k, gr);
                F4U wu; wu.f = *(const float4*)&WSM(s, k, gc);
                ull x0 = pk2(xv.x), x1 = pk2(xv.y);
                ull x2 = pk2(xv.z), x3 = pk2(xv.w);
                fma2(acc[0][0], wu.u[0], x0); fma2(acc[0][1], wu.u[1], x0);
                fma2(acc[1][0], wu.u[0], x1); fma2(acc[1][1], wu.u[1], x1);
                fma2(acc[2][0], wu.u[0], x2); fma2(acc[2][1], wu.u[1], x2);
                fma2(acc[3][0], wu.u[0], x3); fma2(acc[3][1], wu.u[1], x3);
            }
            // fold the loaded batch into the aggregation accumulators
            if (more) {
                if (isNews) {
#pragma unroll
                    for (int t8 = 0; t8 < 8; ++t8) {
                        float w = MW(ar, b * 8 + t8);
                        a0 = fmaf(w, nv[t8].x, a0); a1 = fmaf(w, nv[t8].y, a1);
                        a2 = fmaf(w, nv[t8].z, a2); a3 = fmaf(w, nv[t8].w, a3);
                    }
                } else {
#pragma unroll
                    for (int t8 = 0; t8 < 8; ++t8) {
                        a0 += nv[t8].x; a1 += nv[t8].y;
                        a2 += nv[t8].z; a3 += nv[t8].w;
                    }
                }
            }
        }

        if (more) {
            const float sc = isNews ? 1.f : (1.f / 32.f);
            XSM(1 - s, aj * 4 + 0, ar) = a0 * sc;
            XSM(1 - s, aj * 4 + 1, ar) = a1 * sc;
            XSM(1 - s, aj * 4 + 2, ar) = a2 * sc;
            XSM(1 - s, aj * 4 + 3, ar) = a3 * sc;
#pragma unroll
            for (int q = 0; q < 4; ++q)
                *(float4*)&WSM(1 - s, wkk, wcc + 4 * q) = wpre[q];
        }
        __syncthreads();
    }

    // ---- bias + tanh -> h_s (aliases Ws; last barrier protects) ------------
#pragma unroll
    for (int r = 0; r < 4; ++r)
#pragma unroll
        for (int cp = 0; cp < 2; ++cp) {
            float lo, hi;
            unpk2(acc[r][cp], lo, hi);
            int cc = gc + 2 * cp;
            HS(gr + r, cc)     = tanhf(lo + __ldg(rb + cc));
            HS(gr + r, cc + 1) = tanhf(hi + __ldg(rb + cc + 1));
        }
    __syncthreads();

    // ---------------- GEMM2: hidden = h @ gate_W (32x64) --------------------
    {
        int r2 = tid >> 3;           // 0..31
        int j0 = (tid & 7) * 8;      // 0,8,..,56
        float ha[8];
#pragma unroll
        for (int j = 0; j < 8; ++j) ha[j] = __ldg(gb + j0 + j);
#pragma unroll 8
        for (int k = 0; k < 128; ++k) {
            float hv = HS(r2, k);
            float4 g0 = *(const float4*)(gW + (size_t)k * 64 + j0);
            float4 g1 = *(const float4*)(gW + (size_t)k * 64 + j0 + 4);
            ha[0] = fmaf(hv, g0.x, ha[0]);
            ha[1] = fmaf(hv, g0.y, ha[1]);
            ha[2] = fmaf(hv, g0.z, ha[2]);
            ha[3] = fmaf(hv, g0.w, ha[3]);
            ha[4] = fmaf(hv, g1.x, ha[4]);
            ha[5] = fmaf(hv, g1.y, ha[5]);
            ha[6] = fmaf(hv, g1.z, ha[6]);
            ha[7] = fmaf(hv, g1.w, ha[7]);
        }
        int n = row0 + r2;
        float* ho = out + OFF_HID + (size_t)n * 64 + j0;
#pragma unroll
        for (int j = 0; j < 8; ++j) {
            HID(r2, j0 + j) = ha[j];
            ho[j] = ha[j];
        }
    }
    __syncthreads();

    // ---------------- Epilogue: top2 + routing + sparse expert path ---------
    const int L = lane & 7;
    const int r = wid * 4 + (lane >> 3);
    const int n = row0 + r;

    float v1 = -INFINITY, v2 = -INFINITY;
    int   i1 = 0, i2 = 0;
#pragma unroll
    for (int j = 0; j < 8; ++j) {
        int idx = L * 8 + j;
        float v = HID(r, idx);
        if (v > v1) { v2 = v1; i2 = i1; v1 = v; i1 = idx; }
        else if (v > v2) { v2 = v; i2 = idx; }
    }
#pragma unroll
    for (int d = 1; d <= 4; d <<= 1) {
        float b1 = __shfl_down_sync(0xffffffffu, v1, d, 8);
        int  bi1 = __shfl_down_sync(0xffffffffu, i1, d, 8);
        float b2 = __shfl_down_sync(0xffffffffu, v2, d, 8);
        int  bi2 = __shfl_down_sync(0xffffffffu, i2, d, 8);
        if (b1 > v1) {
            if (v1 >= b2) { v2 = v1; i2 = i1; }
            else          { v2 = b2; i2 = bi2; }
            v1 = b1; i1 = bi1;
        } else if (b1 > v2) {
            v2 = b1; i2 = bi1;
        }
    }
    float rw1 = 0.f, rw2 = 0.f;
    if (L == 0) {
        float e2 = expf(v2 - v1);
        float inv = 1.f / (1.f + e2);
        rw1 = inv;
        rw2 = e2 * inv;
    }
    i1  = __shfl_sync(0xffffffffu, i1, 0, 8);
    i2  = __shfl_sync(0xffffffffu, i2, 0, 8);
    rw1 = __shfl_sync(0xffffffffu, rw1, 0, 8);
    rw2 = __shfl_sync(0xffffffffu, rw2, 0, 8);

#pragma unroll
    for (int j = 0; j < 8; ++j) {
        int idx = L * 8 + j;
        float val = (idx == i1) ? rw1 : ((idx == i2) ? rw2 : 0.f);
        out[OFF_RW1 + (size_t)n * 64 + idx] = val;
        out[OFF_RW2 + (size_t)n * 64 + idx] = val;
    }
    if (L == 0) {
        out[OFF_TK + (size_t)n * 2 + 0] = (float)i1;
        out[OFF_TK + (size_t)n * 2 + 1] = (float)i2;
    }

    float pred = 0.f;
#pragma unroll
    for (int s = 0; s < 2; ++s) {
        int sel  = s ? i2 : i1;
        float rw = s ? rw2 : rw1;
        int g = sel >> 3, f = sel & 7;

        float eo = __ldg(eb + g * 8 + L);
        const float* ew = eW + (size_t)(g * 8 + L) * 64;
#pragma unroll 16
        for (int h = 0; h < 64; ++h)
            eo = fmaf(HID(r, h), __ldg(ew + h), eo);

        float qf = __ldg(wqb + g * 8 + L);
        float kf = __ldg(wkb + g * 8 + L);
        float vf = __ldg(wvb + g * 8 + L);
        const float* wqr = wq + (size_t)(g * 8 + L) * 8;
        const float* wkr = wk + (size_t)(g * 8 + L) * 8;
        const float* wvr = wv + (size_t)(g * 8 + L) * 8;
#pragma unroll
        for (int e = 0; e < 8; ++e) {
            float eoe = __shfl_sync(0xffffffffu, eo, e, 8);
            qf = fmaf(eoe, __ldg(wqr + e), qf);
            kf = fmaf(eoe, __ldg(wkr + e), kf);
            vf = fmaf(eoe, __ldg(wvr + e), vf);
        }
        float q8[8], k8[8], v8[8];
#pragma unroll
        for (int e = 0; e < 8; ++e) {
            q8[e] = __shfl_sync(0xffffffffu, qf, e, 8);
            k8[e] = __shfl_sync(0xffffffffu, kf, e, 8);
            v8[e] = __shfl_sync(0xffffffffu, vf, e, 8);
        }
        float s00 = 0.f, s01 = 0.f, s10 = 0.f, s11 = 0.f;
#pragma unroll
        for (int h = 0; h < 4; ++h) {
            float q0 = q8[2 * h], q1 = q8[2 * h + 1];
            float k0 = k8[2 * h], k1 = k8[2 * h + 1];
            s00 = fmaf(q0, k0, s00); s01 = fmaf(q0, k1, s01);
            s10 = fmaf(q1, k0, s10); s11 = fmaf(q1, k1, s11);
        }
        const float is2 = 0.70710678118654752440f;
        s00 *= is2; s01 *= is2; s10 *= is2; s11 *= is2;
        float m0 = fmaxf(s00, s01);
        float e00 = expf(s00 - m0), e01 = expf(s01 - m0);
        float n0 = 1.f / (e00 + e01);
        float a00 = e00 * n0, a01 = e01 * n0;
        float m1 = fmaxf(s10, s11);
        float e10 = expf(s10 - m1), e11 = expf(s11 - m1);
        float n1 = 1.f / (e10 + e11);
        float a10 = e10 * n1, a11 = e11 * n1;

        float att[8];
#pragma unroll
        for (int h = 0; h < 4; ++h) {
            att[2 * h]     = fmaf(a00, v8[2 * h], a01 * v8[2 * h + 1]);
            att[2 * h + 1] = fmaf(a10, v8[2 * h], a11 * v8[2 * h + 1]);
        }
        float aggf = __ldg(wob + g * 8 + f);
        const float* wor = wo + (size_t)(g * 8 + f) * 8;
#pragma unroll
        for (int e = 0; e < 8; ++e)
            aggf = fmaf(att[e], __ldg(wor + e), aggf);

        pred = fmaf(rw, aggf, pred);
    }
    if (L == 0) out[OFF_PRED + n] = pred;
}

// ---------------------------------------------------------------------------
extern "C" void kernel_launch(void* const* d_in, const int* in_sizes, int n_in,
                              void* d_out, int out_size)
{
    const float* price = (const float*)d_in[0];
    const float* news  = (const float*)d_in[1];
    const float* mask  = (const float*)d_in[2];
    const float* rW    = (const float*)d_in[3];
    const float* rb    = (const float*)d_in[4];
    const float* gW    = (const float*)d_in[5];
    const float* gb    = (const float*)d_in[6];
    const float* eW    = (const float*)d_in[7];
    const float* eb    = (const float*)d_in[8];
    const float* wq    = (const float*)d_in[9];
    const float* wqb   = (const float*)d_in[10];
    const float* wk    = (const float*)d_in[11];
    const float* wkb   = (const float*)d_in[12];
    const float* wv    = (const float*)d_in[13];
    const float* wvb   = (const float*)d_in[14];
    const float* wo    = (const float*)d_in[15];
    const float* wob   = (const float*)d_in[16];
    float* out = (float*)d_out;

    k_fused<<<NROWS / 32, 256>>>(price, news, mask, rW, rb, gW, gb, eW, eb,
                                 wq, wqb, wk, wkb, wv, wvb, wo, wob, out);
}